// round 2
// baseline (speedup 1.0000x reference)
#include <cuda_runtime.h>
#include <math.h>

// ---------------- problem constants ----------------
constexpr int kT   = 1024;
constexpr int kD   = 1024;
constexpr int kH   = 16;
constexpr int kDH  = 64;
constexpr int kE   = 8;
constexpr int kDFF = 4096;
constexpr int kSlots = 2560;   // 2048 assignments + per-expert pad to 64

// ---------------- device scratch (no allocs allowed) ----------------
__device__ float g_x[kT * kD];          // LN1 output
__device__ float g_q[kH * kT * kDH];
__device__ float g_k[kH * kT * kDH];
__device__ float g_v[kH * kT * kDH];
__device__ float g_attn[kT * kD];       // attention output (t, h*DH+e)
__device__ float g_emb2[kT * kD];       // emb + proj(A) + bproj
__device__ float g_y[kT * kD];          // LN2 output
__device__ float g_h[kSlots * kDFF];    // expert hidden
__device__ float g_yo[kSlots * kD];     // expert output per slot
__device__ int   g_ids[kT * 2];
__device__ float g_gates[kT * 2];
__device__ int   g_counts[kE];
__device__ int   g_poff[kE + 1];
__device__ int   g_cursor[kE];
__device__ int   g_slot_token[kSlots];
__device__ int   g_slotpos[kT * 2];
__device__ float g_impsum[kE];

// ---------------- helpers ----------------
__device__ __forceinline__ float block_reduce_sum(float v) {
    __shared__ float sh[32];
    int lane = threadIdx.x & 31, w = threadIdx.x >> 5;
    #pragma unroll
    for (int o = 16; o > 0; o >>= 1) v += __shfl_xor_sync(0xffffffffu, v, o);
    if (lane == 0) sh[w] = v;
    __syncthreads();
    if (w == 0) {
        v = (lane < (int)(blockDim.x >> 5)) ? sh[lane] : 0.f;
        #pragma unroll
        for (int o = 16; o > 0; o >>= 1) v += __shfl_xor_sync(0xffffffffu, v, o);
        if (lane == 0) sh[0] = v;
    }
    __syncthreads();
    float r = sh[0];
    __syncthreads();
    return r;
}

// ---------------- reset ----------------
__global__ void reset_kernel() {
    int i = blockIdx.x * blockDim.x + threadIdx.x;
    if (i < kSlots) g_slot_token[i] = -1;
    if (i < kE) { g_counts[i] = 0; g_impsum[i] = 0.f; }
}

// ---------------- layernorm ----------------
__global__ void ln_kernel(const float* __restrict__ in, const float* __restrict__ g,
                          const float* __restrict__ b, float* __restrict__ out) {
    int row = blockIdx.x;
    const float* x = in + (size_t)row * kD;
    float s = 0.f;
    for (int i = threadIdx.x; i < kD; i += blockDim.x) s += x[i];
    float mean = block_reduce_sum(s) * (1.f / kD);
    float v = 0.f;
    for (int i = threadIdx.x; i < kD; i += blockDim.x) {
        float d = x[i] - mean; v += d * d;
    }
    float var = block_reduce_sum(v) * (1.f / kD);
    float rstd = rsqrtf(var + 1e-6f);
    float* o = out + (size_t)row * kD;
    for (int i = threadIdx.x; i < kD; i += blockDim.x)
        o[i] = (x[i] - mean) * rstd * g[i] + b[i];
}

// ---------------- fused QKV GEMM: per head, C(64t x 64e) = x(64 x 1024) @ W_h ----------------
__global__ void qkv_kernel(const float* __restrict__ x,
                           const float* __restrict__ WQ, const float* __restrict__ WK,
                           const float* __restrict__ WV,
                           float* __restrict__ Qo, float* __restrict__ Ko, float* __restrict__ Vo) {
    const float* W; float* O;
    if (blockIdx.z == 0)      { W = WQ; O = Qo; }
    else if (blockIdx.z == 1) { W = WK; O = Ko; }
    else                      { W = WV; O = Vo; }
    int h = blockIdx.y;
    int r0 = blockIdx.x * 64;
    W += (size_t)h * kD * kDH;
    O += (size_t)h * kT * kDH;

    __shared__ __align__(16) float Ast[16][68];   // [k][row]
    __shared__ __align__(16) float Bs[16][68];    // [k][col]
    int tid = threadIdx.x;
    int tx = tid & 15, ty = tid >> 4;
    float acc[4][4] = {};
    for (int k0 = 0; k0 < kD; k0 += 16) {
        #pragma unroll
        for (int j = 0; j < 4; j++) {
            int e2 = tid + j * 256;
            int row = e2 >> 4, col = e2 & 15;
            Ast[col][row] = x[(size_t)(r0 + row) * kD + k0 + col];
        }
        #pragma unroll
        for (int j = 0; j < 4; j++) {
            int e2 = tid + j * 256;
            int row = e2 >> 6, col = e2 & 63;
            Bs[row][col] = W[(size_t)(k0 + row) * kDH + col];
        }
        __syncthreads();
        #pragma unroll
        for (int k = 0; k < 16; k++) {
            float4 a4 = *(const float4*)&Ast[k][ty * 4];
            float4 b4 = *(const float4*)&Bs[k][tx * 4];
            float av[4] = {a4.x, a4.y, a4.z, a4.w};
            float bv[4] = {b4.x, b4.y, b4.z, b4.w};
            #pragma unroll
            for (int i = 0; i < 4; i++)
                #pragma unroll
                for (int j = 0; j < 4; j++) acc[i][j] += av[i] * bv[j];
        }
        __syncthreads();
    }
    #pragma unroll
    for (int i = 0; i < 4; i++)
        #pragma unroll
        for (int j = 0; j < 4; j++)
            O[(size_t)(r0 + ty * 4 + i) * kDH + tx * 4 + j] = acc[i][j];
}

// ---------------- RoPE (interleaved) ----------------
__global__ void rope_kernel(float* __restrict__ Q, float* __restrict__ Kb) {
    int idx = blockIdx.x * blockDim.x + threadIdx.x;   // over H*T*32 pairs
    if (idx >= kH * kT * (kDH / 2)) return;
    int p = idx & 31;
    int t = (idx >> 5) & (kT - 1);
    size_t base = (size_t)(idx >> 5) * kDH + 2 * p;
    double th  = pow(10000.0, -2.0 * (double)p / (double)kDH);
    double ang = (double)t * th;
    float c = (float)cos(ang), s = (float)sin(ang);
    float q0 = Q[base], q1 = Q[base + 1];
    Q[base]     = q0 * c - q1 * s;
    Q[base + 1] = q1 * c + q0 * s;
    float k0 = Kb[base], k1 = Kb[base + 1];
    Kb[base]     = k0 * c - k1 * s;
    Kb[base + 1] = k1 * c + k0 * s;
}

// ---------------- causal attention, warp per (h, t) row, online softmax ----------------
__global__ void attn_kernel(const float* __restrict__ Q, const float* __restrict__ Kb,
                            const float* __restrict__ V, float* __restrict__ A) {
    int wid = (blockIdx.x * blockDim.x + threadIdx.x) >> 5;
    int lane = threadIdx.x & 31;
    if (wid >= kH * kT) return;
    int h = wid >> 10;
    int t = wid & (kT - 1);
    const float* q = Q + ((size_t)h * kT + t) * kDH;
    float q0 = q[lane], q1 = q[lane + 32];
    const float* Kh = Kb + (size_t)h * kT * kDH;
    const float* Vh = V + (size_t)h * kT * kDH;
    float m = -1e30f, l = 0.f, a0 = 0.f, a1 = 0.f;
    for (int s = 0; s <= t; s++) {
        const float* kr = Kh + (size_t)s * kDH;
        float p = q0 * kr[lane] + q1 * kr[lane + 32];
        #pragma unroll
        for (int o = 16; o > 0; o >>= 1) p += __shfl_xor_sync(0xffffffffu, p, o);
        p *= 0.125f;   // 1/sqrt(64)
        float nm = fmaxf(m, p);
        float scale = __expf(m - nm);
        float w = __expf(p - nm);
        const float* vr = Vh + (size_t)s * kDH;
        a0 = a0 * scale + w * vr[lane];
        a1 = a1 * scale + w * vr[lane + 32];
        l = l * scale + w;
        m = nm;
    }
    float inv = 1.f / l;
    A[(size_t)t * kD + h * kDH + lane]      = a0 * inv;
    A[(size_t)t * kD + h * kDH + lane + 32] = a1 * inv;
}

// ---------------- proj GEMM + residual: emb2 = emb + A@Wproj + bproj ----------------
__global__ void proj_kernel(const float* __restrict__ A, const float* __restrict__ W,
                            const float* __restrict__ bias, const float* __restrict__ emb,
                            float* __restrict__ out) {
    int r0 = blockIdx.x * 64;
    int c0 = blockIdx.y * 64;
    __shared__ __align__(16) float Ast[16][68];
    __shared__ __align__(16) float Bs[16][68];
    int tid = threadIdx.x;
    int tx = tid & 15, ty = tid >> 4;
    float acc[4][4] = {};
    for (int k0 = 0; k0 < kD; k0 += 16) {
        #pragma unroll
        for (int j = 0; j < 4; j++) {
            int e2 = tid + j * 256;
            int row = e2 >> 4, col = e2 & 15;
            Ast[col][row] = A[(size_t)(r0 + row) * kD + k0 + col];
        }
        #pragma unroll
        for (int j = 0; j < 4; j++) {
            int e2 = tid + j * 256;
            int row = e2 >> 6, col = e2 & 63;
            Bs[row][col] = W[(size_t)(k0 + row) * kD + c0 + col];
        }
        __syncthreads();
        #pragma unroll
        for (int k = 0; k < 16; k++) {
            float4 a4 = *(const float4*)&Ast[k][ty * 4];
            float4 b4 = *(const float4*)&Bs[k][tx * 4];
            float av[4] = {a4.x, a4.y, a4.z, a4.w};
            float bv[4] = {b4.x, b4.y, b4.z, b4.w};
            #pragma unroll
            for (int i = 0; i < 4; i++)
                #pragma unroll
                for (int j = 0; j < 4; j++) acc[i][j] += av[i] * bv[j];
        }
        __syncthreads();
    }
    #pragma unroll
    for (int i = 0; i < 4; i++) {
        int r = r0 + ty * 4 + i;
        #pragma unroll
        for (int j = 0; j < 4; j++) {
            int c = c0 + tx * 4 + j;
            out[(size_t)r * kD + c] = emb[(size_t)r * kD + c] + acc[i][j] + bias[c];
        }
    }
}

// ---------------- router: warp per token ----------------
__global__ void router_kernel(const float* __restrict__ y, const float* __restrict__ Wr,
                              const float* __restrict__ br) {
    int warp = (blockIdx.x * blockDim.x + threadIdx.x) >> 5;
    int lane = threadIdx.x & 31;
    if (warp >= kT) return;
    const float* yr = y + (size_t)warp * kD;
    float s[kE];
    #pragma unroll
    for (int e = 0; e < kE; e++) s[e] = 0.f;
    for (int d = lane; d < kD; d += 32) {
        float yv = yr[d];
        const float* wr = Wr + (size_t)d * kE;
        #pragma unroll
        for (int e = 0; e < kE; e++) s[e] += yv * wr[e];
    }
    #pragma unroll
    for (int e = 0; e < kE; e++) {
        float v = s[e];
        #pragma unroll
        for (int o = 16; o > 0; o >>= 1) v += __shfl_xor_sync(0xffffffffu, v, o);
        s[e] = v;
    }
    if (lane == 0) {
        float w[kE];
        float mx = -1e30f;
        #pragma unroll
        for (int e = 0; e < kE; e++) { w[e] = s[e] + br[e]; mx = fmaxf(mx, w[e]); }
        float sum = 0.f;
        #pragma unroll
        for (int e = 0; e < kE; e++) { w[e] = __expf(w[e] - mx); sum += w[e]; }
        float inv = 1.f / sum;
        #pragma unroll
        for (int e = 0; e < kE; e++) w[e] *= inv;
        int i0 = 0;
        #pragma unroll
        for (int e = 1; e < kE; e++) if (w[e] > w[i0]) i0 = e;
        int i1 = -1;
        #pragma unroll
        for (int e = 0; e < kE; e++) if (e != i0 && (i1 < 0 || w[e] > w[i1])) i1 = e;
        float norm = w[i0] + w[i1];
        g_ids[warp * 2]     = i0;
        g_ids[warp * 2 + 1] = i1;
        g_gates[warp * 2]     = w[i0] / norm;
        g_gates[warp * 2 + 1] = w[i1] / norm;
        atomicAdd(&g_counts[i0], 1);
        atomicAdd(&g_counts[i1], 1);
        #pragma unroll
        for (int e = 0; e < kE; e++) atomicAdd(&g_impsum[e], w[e]);
    }
}

// ---------------- offsets + aux ----------------
__global__ void offsets_kernel(float* __restrict__ out, int out_size) {
    if (threadIdx.x == 0 && blockIdx.x == 0) {
        int off = 0;
        g_poff[0] = 0;
        for (int e = 0; e < kE; e++) {
            int pc = (g_counts[e] + 63) & ~63;
            off += pc;
            g_poff[e + 1] = off;
            g_cursor[e] = g_poff[e];
        }
        float aux = 0.f;
        for (int e = 0; e < kE; e++) {
            float imp = g_impsum[e] / (float)kT;
            float dlt = imp - 1.f / (float)kE;
            aux += dlt * dlt;
        }
        aux *= 1.f / (float)kE;
        if (out_size > kT * kD) out[kT * kD] = aux;
    }
}

// ---------------- scatter tokens into expert-grouped slots ----------------
__global__ void scatter_kernel() {
    int i = blockIdx.x * blockDim.x + threadIdx.x;
    if (i >= kT * 2) return;
    int e = g_ids[i];
    int pos = atomicAdd(&g_cursor[e], 1);
    g_slot_token[pos] = i >> 1;
    g_slotpos[i] = pos;
}

// ---------------- F1: h = relu(y_gathered @ W1[e] + b1[e]) ----------------
__global__ void f1_kernel(const float* __restrict__ y, const float* __restrict__ W1,
                          const float* __restrict__ b1) {
    __shared__ __align__(16) float Ast[16][68];
    __shared__ __align__(16) float Bs[16][68];
    __shared__ int poff_s[kE + 1];
    __shared__ int tok[64];
    int tid = threadIdx.x;
    int s0 = blockIdx.x * 64;
    if (tid <= kE) poff_s[tid] = g_poff[tid];
    if (tid < 64) tok[tid] = g_slot_token[s0 + tid];
    __syncthreads();
    int total = poff_s[kE];
    if (s0 >= total) return;
    int e = 0;
    while (s0 >= poff_s[e + 1]) e++;
    const float* W = W1 + (size_t)e * kD * kDFF;
    int f0 = blockIdx.y * 64;

    int tx = tid & 15, ty = tid >> 4;
    float acc[4][4] = {};
    for (int k0 = 0; k0 < kD; k0 += 16) {
        #pragma unroll
        for (int j = 0; j < 4; j++) {
            int e2 = tid + j * 256;
            int row = e2 >> 4, col = e2 & 15;
            int t = tok[row];
            Ast[col][row] = (t >= 0) ? y[(size_t)t * kD + k0 + col] : 0.f;
        }
        #pragma unroll
        for (int j = 0; j < 4; j++) {
            int e2 = tid + j * 256;
            int row = e2 >> 6, col = e2 & 63;
            Bs[row][col] = W[(size_t)(k0 + row) * kDFF + f0 + col];
        }
        __syncthreads();
        #pragma unroll
        for (int k = 0; k < 16; k++) {
            float4 a4 = *(const float4*)&Ast[k][ty * 4];
            float4 b4 = *(const float4*)&Bs[k][tx * 4];
            float av[4] = {a4.x, a4.y, a4.z, a4.w};
            float bv[4] = {b4.x, b4.y, b4.z, b4.w};
            #pragma unroll
            for (int i = 0; i < 4; i++)
                #pragma unroll
                for (int j = 0; j < 4; j++) acc[i][j] += av[i] * bv[j];
        }
        __syncthreads();
    }
    #pragma unroll
    for (int i = 0; i < 4; i++) {
        int r = s0 + ty * 4 + i;
        #pragma unroll
        for (int j = 0; j < 4; j++) {
            int c = f0 + tx * 4 + j;
            float v = acc[i][j] + b1[(size_t)e * kDFF + c];
            g_h[(size_t)r * kDFF + c] = fmaxf(v, 0.f);
        }
    }
}

// ---------------- F2: yo = h @ W2[e] + b2[e] ----------------
__global__ void f2_kernel(const float* __restrict__ W2, const float* __restrict__ b2) {
    __shared__ __align__(16) float Ast[16][68];
    __shared__ __align__(16) float Bs[16][68];
    __shared__ int poff_s[kE + 1];
    int tid = threadIdx.x;
    int s0 = blockIdx.x * 64;
    if (tid <= kE) poff_s[tid] = g_poff[tid];
    __syncthreads();
    int total = poff_s[kE];
    if (s0 >= total) return;
    int e = 0;
    while (s0 >= poff_s[e + 1]) e++;
    const float* W = W2 + (size_t)e * kDFF * kD;
    int c0 = blockIdx.y * 64;

    int tx = tid & 15, ty = tid >> 4;
    float acc[4][4] = {};
    for (int k0 = 0; k0 < kDFF; k0 += 16) {
        #pragma unroll
        for (int j = 0; j < 4; j++) {
            int e2 = tid + j * 256;
            int row = e2 >> 4, col = e2 & 15;
            Ast[col][row] = g_h[(size_t)(s0 + row) * kDFF + k0 + col];
        }
        #pragma unroll
        for (int j = 0; j < 4; j++) {
            int e2 = tid + j * 256;
            int row = e2 >> 6, col = e2 & 63;
            Bs[row][col] = W[(size_t)(k0 + row) * kD + c0 + col];
        }
        __syncthreads();
        #pragma unroll
        for (int k = 0; k < 16; k++) {
            float4 a4 = *(const float4*)&Ast[k][ty * 4];
            float4 b4 = *(const float4*)&Bs[k][tx * 4];
            float av[4] = {a4.x, a4.y, a4.z, a4.w};
            float bv[4] = {b4.x, b4.y, b4.z, b4.w};
            #pragma unroll
            for (int i = 0; i < 4; i++)
                #pragma unroll
                for (int j = 0; j < 4; j++) acc[i][j] += av[i] * bv[j];
        }
        __syncthreads();
    }
    #pragma unroll
    for (int i = 0; i < 4; i++) {
        int r = s0 + ty * 4 + i;
        #pragma unroll
        for (int j = 0; j < 4; j++) {
            int c = c0 + tx * 4 + j;
            g_yo[(size_t)r * kD + c] = acc[i][j] + b2[(size_t)e * kD + c];
        }
    }
}

// ---------------- combine: out = emb2 + g0*yo[slot0] + g1*yo[slot1] ----------------
__global__ void combine_kernel(float* __restrict__ out) {
    int idx4 = blockIdx.x * blockDim.x + threadIdx.x;   // over T*D/4
    if (idx4 >= kT * kD / 4) return;
    int idx = idx4 * 4;
    int n = idx >> 10;      // token
    int d = idx & (kD - 1);
    int p0 = g_slotpos[n * 2], p1 = g_slotpos[n * 2 + 1];
    float g0 = g_gates[n * 2], g1 = g_gates[n * 2 + 1];
    float4 base = *(const float4*)&g_emb2[idx];
    float4 y0 = *(const float4*)&g_yo[(size_t)p0 * kD + d];
    float4 y1 = *(const float4*)&g_yo[(size_t)p1 * kD + d];
    float4 r;
    r.x = base.x + g0 * y0.x + g1 * y1.x;
    r.y = base.y + g0 * y0.y + g1 * y1.y;
    r.z = base.z + g0 * y0.z + g1 * y1.z;
    r.w = base.w + g0 * y0.w + g1 * y1.w;
    *(float4*)&out[idx] = r;
}

// ---------------- launch ----------------
extern "C" void kernel_launch(void* const* d_in, const int* in_sizes, int n_in,
                              void* d_out, int out_size) {
    const float* emb    = (const float*)d_in[0];
    const float* gamma1 = (const float*)d_in[1];
    const float* beta1  = (const float*)d_in[2];
    const float* WQ     = (const float*)d_in[3];
    const float* WK     = (const float*)d_in[4];
    const float* WV     = (const float*)d_in[5];
    const float* Wproj  = (const float*)d_in[6];
    const float* bproj  = (const float*)d_in[7];
    const float* gamma2 = (const float*)d_in[8];
    const float* beta2  = (const float*)d_in[9];
    const float* Wr     = (const float*)d_in[10];
    const float* br     = (const float*)d_in[11];
    const float* W1     = (const float*)d_in[12];
    const float* b1     = (const float*)d_in[13];
    const float* W2     = (const float*)d_in[14];
    const float* b2     = (const float*)d_in[15];
    float* out = (float*)d_out;

    float* gx;    cudaGetSymbolAddress((void**)&gx, g_x);
    float* gq;    cudaGetSymbolAddress((void**)&gq, g_q);
    float* gk;    cudaGetSymbolAddress((void**)&gk, g_k);
    float* gv;    cudaGetSymbolAddress((void**)&gv, g_v);
    float* gattn; cudaGetSymbolAddress((void**)&gattn, g_attn);
    float* gemb2; cudaGetSymbolAddress((void**)&gemb2, g_emb2);
    float* gy;    cudaGetSymbolAddress((void**)&gy, g_y);

    reset_kernel<<<(kSlots + 255) / 256, 256>>>();
    ln_kernel<<<kT, 256>>>(emb, gamma1, beta1, gx);
    qkv_kernel<<<dim3(kT / 64, kH, 3), 256>>>(gx, WQ, WK, WV, gq, gk, gv);
    rope_kernel<<<(kH * kT * 32 + 255) / 256, 256>>>(gq, gk);
    attn_kernel<<<(kH * kT) / 8, 256>>>(gq, gk, gv, gattn);
    proj_kernel<<<dim3(kT / 64, kD / 64), 256>>>(gattn, Wproj, bproj, emb, gemb2);
    ln_kernel<<<kT, 256>>>(gemb2, gamma2, beta2, gy);
    router_kernel<<<kT / 8, 256>>>(gy, Wr, br);
    offsets_kernel<<<1, 32>>>(out, out_size);
    scatter_kernel<<<(kT * 2 + 255) / 256, 256>>>();
    f1_kernel<<<dim3(kSlots / 64, kDFF / 64), 256>>>(gy, W1, b1);
    f2_kernel<<<dim3(kSlots / 64, kD / 64), 256>>>(W2, b2);
    combine_kernel<<<(kT * kD / 4 + 255) / 256, 256>>>(out);
}

// round 3
// speedup vs baseline: 1.7273x; 1.7273x over previous
#include <cuda_runtime.h>
#include <math.h>

// ---------------- problem constants ----------------
constexpr int kT   = 1024;
constexpr int kD   = 1024;
constexpr int kH   = 16;
constexpr int kDH  = 64;
constexpr int kE   = 8;
constexpr int kDFF = 4096;
constexpr int kSlots = 3072;   // 2048 assignments + per-expert pad to 128

// ---------------- device scratch ----------------
__device__ float g_x[kT * kD];
__device__ float g_q[kH * kT * kDH];
__device__ float g_k[kH * kT * kDH];
__device__ float g_v[kH * kT * kDH];
__device__ float g_attn[kT * kD];
__device__ float g_emb2[kT * kD];
__device__ float g_y[kT * kD];
__device__ float g_h[kSlots * kDFF];
__device__ float g_yo[kSlots * kD];
__device__ int   g_ids[kT * 2];
__device__ float g_gates[kT * 2];
__device__ int   g_counts[kE];
__device__ int   g_poff[kE + 1];
__device__ int   g_cursor[kE];
__device__ int   g_slot_token[kSlots];
__device__ int   g_slotpos[kT * 2];
__device__ float g_impsum[kE];

// ---------------- mma helpers ----------------
__device__ __forceinline__ unsigned f2tf32(float x) {
    unsigned y; asm("cvt.rna.tf32.f32 %0, %1;" : "=r"(y) : "f"(x)); return y;
}
__device__ __forceinline__ void mma_tf32(float c[4], const unsigned a[4], const unsigned b[2]) {
    asm volatile("mma.sync.aligned.m16n8k8.row.col.f32.tf32.tf32.f32 "
        "{%0,%1,%2,%3}, {%4,%5,%6,%7}, {%8,%9}, {%0,%1,%2,%3};\n"
        : "+f"(c[0]), "+f"(c[1]), "+f"(c[2]), "+f"(c[3])
        : "r"(a[0]), "r"(a[1]), "r"(a[2]), "r"(a[3]), "r"(b[0]), "r"(b[1]));
}

// Shared GEMM tile config: block 256 threads, tile M=128 N=128, K-panel 32.
// Warp (w = tid>>5): wm = w&3 (M group of 32 rows), wn = w>>2 (N group of 64 cols).
constexpr int ASTRIDE = 36;    // [m][36] -> frag-load bank == lane (conflict-free)
constexpr int BSTRIDE = 136;   // [k][136] -> frag-load banks 8*(l&3)+(l>>2) (conflict-free)

#define GEMM_SMEM \
    __shared__ __align__(16) unsigned As[128 * ASTRIDE]; \
    __shared__ __align__(16) unsigned Bs[32 * BSTRIDE];

#define GEMM_COMPUTE_PANEL \
    _Pragma("unroll") \
    for (int kk = 0; kk < 32; kk += 8) { \
        unsigned bf[8][2]; \
        _Pragma("unroll") \
        for (int nt = 0; nt < 8; nt++) { \
            int n = wn * 64 + nt * 8 + (lane >> 2); \
            bf[nt][0] = Bs[(kk + (lane & 3)) * BSTRIDE + n]; \
            bf[nt][1] = Bs[(kk + 4 + (lane & 3)) * BSTRIDE + n]; \
        } \
        _Pragma("unroll") \
        for (int mt = 0; mt < 2; mt++) { \
            int m = wm * 32 + mt * 16 + (lane >> 2); \
            unsigned af[4]; \
            af[0] = As[m * ASTRIDE + kk + (lane & 3)]; \
            af[1] = As[(m + 8) * ASTRIDE + kk + (lane & 3)]; \
            af[2] = As[m * ASTRIDE + kk + 4 + (lane & 3)]; \
            af[3] = As[(m + 8) * ASTRIDE + kk + 4 + (lane & 3)]; \
            _Pragma("unroll") \
            for (int nt = 0; nt < 8; nt++) mma_tf32(acc[mt][nt], af, bf[nt]); \
        } \
    }

__device__ __forceinline__ void store_a_frag4(unsigned* As, int m, int kv4, float4 v) {
    uint4 u = { f2tf32(v.x), f2tf32(v.y), f2tf32(v.z), f2tf32(v.w) };
    *(uint4*)&As[m * ASTRIDE + kv4] = u;
}
__device__ __forceinline__ void store_b_frag4(unsigned* Bs, int k, int nv4, float4 v) {
    uint4 u = { f2tf32(v.x), f2tf32(v.y), f2tf32(v.z), f2tf32(v.w) };
    *(uint4*)&Bs[k * BSTRIDE + nv4] = u;
}

// ---------------- misc helpers ----------------
__device__ __forceinline__ float block_reduce_sum(float v) {
    __shared__ float sh[32];
    int lane = threadIdx.x & 31, w = threadIdx.x >> 5;
    #pragma unroll
    for (int o = 16; o > 0; o >>= 1) v += __shfl_xor_sync(0xffffffffu, v, o);
    if (lane == 0) sh[w] = v;
    __syncthreads();
    if (w == 0) {
        v = (lane < (int)(blockDim.x >> 5)) ? sh[lane] : 0.f;
        #pragma unroll
        for (int o = 16; o > 0; o >>= 1) v += __shfl_xor_sync(0xffffffffu, v, o);
        if (lane == 0) sh[0] = v;
    }
    __syncthreads();
    float r = sh[0];
    __syncthreads();
    return r;
}

__global__ void reset_kernel() {
    int i = blockIdx.x * blockDim.x + threadIdx.x;
    if (i < kSlots) g_slot_token[i] = -1;
    if (i < kE) { g_counts[i] = 0; g_impsum[i] = 0.f; }
}

__global__ void ln_kernel(const float* __restrict__ in, const float* __restrict__ g,
                          const float* __restrict__ b, float* __restrict__ out) {
    int row = blockIdx.x;
    const float* x = in + (size_t)row * kD;
    float s = 0.f;
    for (int i = threadIdx.x; i < kD; i += blockDim.x) s += x[i];
    float mean = block_reduce_sum(s) * (1.f / kD);
    float v = 0.f;
    for (int i = threadIdx.x; i < kD; i += blockDim.x) {
        float d = x[i] - mean; v += d * d;
    }
    float var = block_reduce_sum(v) * (1.f / kD);
    float rstd = rsqrtf(var + 1e-6f);
    float* o = out + (size_t)row * kD;
    for (int i = threadIdx.x; i < kD; i += blockDim.x)
        o[i] = (x[i] - mean) * rstd * g[i] + b[i];
}

// ---------------- QKV tf32 GEMM + fused RoPE ----------------
// grid (T/128, HD/128, 3). Per head N=64, so one N tile covers 2 heads.
__global__ __launch_bounds__(256) void qkv_kernel(
    const float* __restrict__ x,
    const float* __restrict__ WQ, const float* __restrict__ WK, const float* __restrict__ WV,
    float* __restrict__ Qo, float* __restrict__ Ko, float* __restrict__ Vo) {
    GEMM_SMEM
    int tid = threadIdx.x, lane = tid & 31, w = tid >> 5;
    int wm = w & 3, wn = w >> 2;
    int r0 = blockIdx.x * 128;
    int n0 = blockIdx.y * 128;
    int z = blockIdx.z;
    const float* W = (z == 0) ? WQ : (z == 1) ? WK : WV;
    float* O = (z == 0) ? Qo : (z == 1) ? Ko : Vo;

    float acc[2][8][4] = {};
    for (int k0 = 0; k0 < kD; k0 += 32) {
        #pragma unroll
        for (int p = 0; p < 4; p++) {
            int m = (tid >> 3) + p * 32, kv = (tid & 7) * 4;
            float4 v = *(const float4*)&x[(size_t)(r0 + m) * kD + k0 + kv];
            store_a_frag4(As, m, kv, v);
        }
        #pragma unroll
        for (int p = 0; p < 4; p++) {
            int kr = (tid >> 5) + p * 8, nv = (tid & 31) * 4;
            int n = n0 + nv;
            int h = n >> 6, e = n & 63;
            float4 v = *(const float4*)&W[((size_t)h * kD + k0 + kr) * kDH + e];
            store_b_frag4(Bs, kr, nv, v);
        }
        __syncthreads();
        GEMM_COMPUTE_PANEL
        __syncthreads();
    }
    // epilogue: rope for Q,K; plain for V. Each thread owns (even,odd) col pairs.
    #pragma unroll
    for (int mt = 0; mt < 2; mt++) {
        #pragma unroll
        for (int nt = 0; nt < 8; nt++) {
            int n = n0 + wn * 64 + nt * 8 + (lane & 3) * 2;
            int h = n >> 6, e = n & 63;
            #pragma unroll
            for (int half = 0; half < 2; half++) {
                int t = r0 + wm * 32 + mt * 16 + (lane >> 2) + half * 8;
                float v0 = acc[mt][nt][half * 2 + 0];
                float v1 = acc[mt][nt][half * 2 + 1];
                if (z < 2) {
                    int p = e >> 1;
                    float theta = exp2f(-(float)p * (13.287712379549449f / 32.f));
                    float sn, cs;
                    sincosf((float)t * theta, &sn, &cs);
                    float w0 = v0 * cs - v1 * sn;
                    float w1 = v1 * cs + v0 * sn;
                    v0 = w0; v1 = w1;
                }
                float2 r2 = { v0, v1 };
                *(float2*)&O[((size_t)h * kT + t) * kDH + e] = r2;
            }
        }
    }
}

// ---------------- causal attention, warp per (h, t) row, online softmax ----------------
__global__ void attn_kernel(const float* __restrict__ Q, const float* __restrict__ Kb,
                            const float* __restrict__ V, float* __restrict__ A) {
    int wid = (blockIdx.x * blockDim.x + threadIdx.x) >> 5;
    int lane = threadIdx.x & 31;
    if (wid >= kH * kT) return;
    int h = wid >> 10;
    int t = wid & (kT - 1);
    const float* q = Q + ((size_t)h * kT + t) * kDH;
    float q0 = q[lane], q1 = q[lane + 32];
    const float* Kh = Kb + (size_t)h * kT * kDH;
    const float* Vh = V + (size_t)h * kT * kDH;
    float m = -1e30f, l = 0.f, a0 = 0.f, a1 = 0.f;
    for (int s = 0; s <= t; s++) {
        const float* kr = Kh + (size_t)s * kDH;
        float p = q0 * kr[lane] + q1 * kr[lane + 32];
        #pragma unroll
        for (int o = 16; o > 0; o >>= 1) p += __shfl_xor_sync(0xffffffffu, p, o);
        p *= 0.125f;
        float nm = fmaxf(m, p);
        float scale = __expf(m - nm);
        float w = __expf(p - nm);
        const float* vr = Vh + (size_t)s * kDH;
        a0 = a0 * scale + w * vr[lane];
        a1 = a1 * scale + w * vr[lane + 32];
        l = l * scale + w;
        m = nm;
    }
    float inv = 1.f / l;
    A[(size_t)t * kD + h * kDH + lane]      = a0 * inv;
    A[(size_t)t * kD + h * kDH + lane + 32] = a1 * inv;
}

// ---------------- proj tf32 GEMM + residual ----------------
__global__ __launch_bounds__(256) void proj_kernel(
    const float* __restrict__ A, const float* __restrict__ W,
    const float* __restrict__ bias, const float* __restrict__ emb,
    float* __restrict__ out) {
    GEMM_SMEM
    int tid = threadIdx.x, lane = tid & 31, w = tid >> 5;
    int wm = w & 3, wn = w >> 2;
    int r0 = blockIdx.x * 128;
    int n0 = blockIdx.y * 128;

    float acc[2][8][4] = {};
    for (int k0 = 0; k0 < kD; k0 += 32) {
        #pragma unroll
        for (int p = 0; p < 4; p++) {
            int m = (tid >> 3) + p * 32, kv = (tid & 7) * 4;
            float4 v = *(const float4*)&A[(size_t)(r0 + m) * kD + k0 + kv];
            store_a_frag4(As, m, kv, v);
        }
        #pragma unroll
        for (int p = 0; p < 4; p++) {
            int kr = (tid >> 5) + p * 8, nv = (tid & 31) * 4;
            float4 v = *(const float4*)&W[(size_t)(k0 + kr) * kD + n0 + nv];
            store_b_frag4(Bs, kr, nv, v);
        }
        __syncthreads();
        GEMM_COMPUTE_PANEL
        __syncthreads();
    }
    #pragma unroll
    for (int mt = 0; mt < 2; mt++) {
        #pragma unroll
        for (int nt = 0; nt < 8; nt++) {
            int c = n0 + wn * 64 + nt * 8 + (lane & 3) * 2;
            #pragma unroll
            for (int half = 0; half < 2; half++) {
                int r = r0 + wm * 32 + mt * 16 + (lane >> 2) + half * 8;
                float2 e2 = *(const float2*)&emb[(size_t)r * kD + c];
                float2 r2;
                r2.x = e2.x + acc[mt][nt][half * 2 + 0] + bias[c];
                r2.y = e2.y + acc[mt][nt][half * 2 + 1] + bias[c + 1];
                *(float2*)&out[(size_t)r * kD + c] = r2;
            }
        }
    }
}

// ---------------- router ----------------
__global__ void router_kernel(const float* __restrict__ y, const float* __restrict__ Wr,
                              const float* __restrict__ br) {
    int warp = (blockIdx.x * blockDim.x + threadIdx.x) >> 5;
    int lane = threadIdx.x & 31;
    if (warp >= kT) return;
    const float* yr = y + (size_t)warp * kD;
    float s[kE];
    #pragma unroll
    for (int e = 0; e < kE; e++) s[e] = 0.f;
    for (int d = lane; d < kD; d += 32) {
        float yv = yr[d];
        const float* wr = Wr + (size_t)d * kE;
        #pragma unroll
        for (int e = 0; e < kE; e++) s[e] += yv * wr[e];
    }
    #pragma unroll
    for (int e = 0; e < kE; e++) {
        float v = s[e];
        #pragma unroll
        for (int o = 16; o > 0; o >>= 1) v += __shfl_xor_sync(0xffffffffu, v, o);
        s[e] = v;
    }
    if (lane == 0) {
        float w[kE];
        float mx = -1e30f;
        #pragma unroll
        for (int e = 0; e < kE; e++) { w[e] = s[e] + br[e]; mx = fmaxf(mx, w[e]); }
        float sum = 0.f;
        #pragma unroll
        for (int e = 0; e < kE; e++) { w[e] = __expf(w[e] - mx); sum += w[e]; }
        float inv = 1.f / sum;
        #pragma unroll
        for (int e = 0; e < kE; e++) w[e] *= inv;
        int i0 = 0;
        #pragma unroll
        for (int e = 1; e < kE; e++) if (w[e] > w[i0]) i0 = e;
        int i1 = -1;
        #pragma unroll
        for (int e = 0; e < kE; e++) if (e != i0 && (i1 < 0 || w[e] > w[i1])) i1 = e;
        float norm = w[i0] + w[i1];
        g_ids[warp * 2]     = i0;
        g_ids[warp * 2 + 1] = i1;
        g_gates[warp * 2]     = w[i0] / norm;
        g_gates[warp * 2 + 1] = w[i1] / norm;
        atomicAdd(&g_counts[i0], 1);
        atomicAdd(&g_counts[i1], 1);
        #pragma unroll
        for (int e = 0; e < kE; e++) atomicAdd(&g_impsum[e], w[e]);
    }
}

__global__ void offsets_kernel(float* __restrict__ out, int out_size) {
    if (threadIdx.x == 0 && blockIdx.x == 0) {
        int off = 0;
        g_poff[0] = 0;
        for (int e = 0; e < kE; e++) {
            int pc = (g_counts[e] + 127) & ~127;
            off += pc;
            g_poff[e + 1] = off;
            g_cursor[e] = g_poff[e];
        }
        float aux = 0.f;
        for (int e = 0; e < kE; e++) {
            float imp = g_impsum[e] / (float)kT;
            float dlt = imp - 1.f / (float)kE;
            aux += dlt * dlt;
        }
        aux *= 1.f / (float)kE;
        if (out_size > kT * kD) out[kT * kD] = aux;
    }
}

__global__ void scatter_kernel() {
    int i = blockIdx.x * blockDim.x + threadIdx.x;
    if (i >= kT * 2) return;
    int e = g_ids[i];
    int pos = atomicAdd(&g_cursor[e], 1);
    g_slot_token[pos] = i >> 1;
    g_slotpos[i] = pos;
}

// ---------------- F1: h = relu(y_gathered @ W1[e] + b1[e]) tf32 ----------------
__global__ __launch_bounds__(256) void f1_kernel(
    const float* __restrict__ y, const float* __restrict__ W1,
    const float* __restrict__ b1) {
    GEMM_SMEM
    __shared__ int tok[128];
    __shared__ int sh_total, sh_e;
    int tid = threadIdx.x, lane = tid & 31, w = tid >> 5;
    int wm = w & 3, wn = w >> 2;
    int s0 = blockIdx.x * 128;
    if (tid == 0) {
        sh_total = g_poff[kE];
        int e = 0;
        while (e < kE - 1 && s0 >= g_poff[e + 1]) e++;
        sh_e = e;
    }
    if (tid < 128) tok[tid] = g_slot_token[s0 + tid];
    __syncthreads();
    if (s0 >= sh_total) return;
    int e = sh_e;
    const float* W = W1 + (size_t)e * kD * kDFF;
    int f0 = blockIdx.y * 128;

    float acc[2][8][4] = {};
    for (int k0 = 0; k0 < kD; k0 += 32) {
        #pragma unroll
        for (int p = 0; p < 4; p++) {
            int m = (tid >> 3) + p * 32, kv = (tid & 7) * 4;
            int t = tok[m];
            float4 v = (t >= 0) ? *(const float4*)&y[(size_t)t * kD + k0 + kv]
                                : make_float4(0.f, 0.f, 0.f, 0.f);
            store_a_frag4(As, m, kv, v);
        }
        #pragma unroll
        for (int p = 0; p < 4; p++) {
            int kr = (tid >> 5) + p * 8, nv = (tid & 31) * 4;
            float4 v = *(const float4*)&W[(size_t)(k0 + kr) * kDFF + f0 + nv];
            store_b_frag4(Bs, kr, nv, v);
        }
        __syncthreads();
        GEMM_COMPUTE_PANEL
        __syncthreads();
    }
    #pragma unroll
    for (int mt = 0; mt < 2; mt++) {
        #pragma unroll
        for (int nt = 0; nt < 8; nt++) {
            int c = f0 + wn * 64 + nt * 8 + (lane & 3) * 2;
            float bb0 = b1[(size_t)e * kDFF + c];
            float bb1 = b1[(size_t)e * kDFF + c + 1];
            #pragma unroll
            for (int half = 0; half < 2; half++) {
                int r = s0 + wm * 32 + mt * 16 + (lane >> 2) + half * 8;
                float2 r2;
                r2.x = fmaxf(acc[mt][nt][half * 2 + 0] + bb0, 0.f);
                r2.y = fmaxf(acc[mt][nt][half * 2 + 1] + bb1, 0.f);
                *(float2*)&g_h[(size_t)r * kDFF + c] = r2;
            }
        }
    }
}

// ---------------- F2: yo = h @ W2[e] + b2[e] tf32 ----------------
__global__ __launch_bounds__(256) void f2_kernel(
    const float* __restrict__ W2, const float* __restrict__ b2) {
    GEMM_SMEM
    __shared__ int sh_total, sh_e;
    int tid = threadIdx.x, lane = tid & 31, w = tid >> 5;
    int wm = w & 3, wn = w >> 2;
    int s0 = blockIdx.x * 128;
    if (tid == 0) {
        sh_total = g_poff[kE];
        int e = 0;
        while (e < kE - 1 && s0 >= g_poff[e + 1]) e++;
        sh_e = e;
    }
    __syncthreads();
    if (s0 >= sh_total) return;
    int e = sh_e;
    const float* W = W2 + (size_t)e * kDFF * kD;
    int c0 = blockIdx.y * 128;

    float acc[2][8][4] = {};
    for (int k0 = 0; k0 < kDFF; k0 += 32) {
        #pragma unroll
        for (int p = 0; p < 4; p++) {
            int m = (tid >> 3) + p * 32, kv = (tid & 7) * 4;
            float4 v = *(const float4*)&g_h[(size_t)(s0 + m) * kDFF + k0 + kv];
            store_a_frag4(As, m, kv, v);
        }
        #pragma unroll
        for (int p = 0; p < 4; p++) {
            int kr = (tid >> 5) + p * 8, nv = (tid & 31) * 4;
            float4 v = *(const float4*)&W[(size_t)(k0 + kr) * kD + c0 + nv];
            store_b_frag4(Bs, kr, nv, v);
        }
        __syncthreads();
        GEMM_COMPUTE_PANEL
        __syncthreads();
    }
    #pragma unroll
    for (int mt = 0; mt < 2; mt++) {
        #pragma unroll
        for (int nt = 0; nt < 8; nt++) {
            int c = c0 + wn * 64 + nt * 8 + (lane & 3) * 2;
            float bb0 = b2[(size_t)e * kD + c];
            float bb1 = b2[(size_t)e * kD + c + 1];
            #pragma unroll
            for (int half = 0; half < 2; half++) {
                int r = s0 + wm * 32 + mt * 16 + (lane >> 2) + half * 8;
                float2 r2;
                r2.x = acc[mt][nt][half * 2 + 0] + bb0;
                r2.y = acc[mt][nt][half * 2 + 1] + bb1;
                *(float2*)&g_yo[(size_t)r * kD + c] = r2;
            }
        }
    }
}

// ---------------- combine ----------------
__global__ void combine_kernel(float* __restrict__ out) {
    int idx4 = blockIdx.x * blockDim.x + threadIdx.x;
    if (idx4 >= kT * kD / 4) return;
    int idx = idx4 * 4;
    int n = idx >> 10;
    int d = idx & (kD - 1);
    int p0 = g_slotpos[n * 2], p1 = g_slotpos[n * 2 + 1];
    float g0 = g_gates[n * 2], g1 = g_gates[n * 2 + 1];
    float4 base = *(const float4*)&g_emb2[idx];
    float4 y0 = *(const float4*)&g_yo[(size_t)p0 * kD + d];
    float4 y1 = *(const float4*)&g_yo[(size_t)p1 * kD + d];
    float4 r;
    r.x = base.x + g0 * y0.x + g1 * y1.x;
    r.y = base.y + g0 * y0.y + g1 * y1.y;
    r.z = base.z + g0 * y0.z + g1 * y1.z;
    r.w = base.w + g0 * y0.w + g1 * y1.w;
    *(float4*)&out[idx] = r;
}

// ---------------- launch ----------------
extern "C" void kernel_launch(void* const* d_in, const int* in_sizes, int n_in,
                              void* d_out, int out_size) {
    const float* emb    = (const float*)d_in[0];
    const float* gamma1 = (const float*)d_in[1];
    const float* beta1  = (const float*)d_in[2];
    const float* WQ     = (const float*)d_in[3];
    const float* WK     = (const float*)d_in[4];
    const float* WV     = (const float*)d_in[5];
    const float* Wproj  = (const float*)d_in[6];
    const float* bproj  = (const float*)d_in[7];
    const float* gamma2 = (const float*)d_in[8];
    const float* beta2  = (const float*)d_in[9];
    const float* Wr     = (const float*)d_in[10];
    const float* br     = (const float*)d_in[11];
    const float* W1     = (const float*)d_in[12];
    const float* b1     = (const float*)d_in[13];
    const float* W2     = (const float*)d_in[14];
    const float* b2     = (const float*)d_in[15];
    float* out = (float*)d_out;

    float* gx;    cudaGetSymbolAddress((void**)&gx, g_x);
    float* gq;    cudaGetSymbolAddress((void**)&gq, g_q);
    float* gk;    cudaGetSymbolAddress((void**)&gk, g_k);
    float* gv;    cudaGetSymbolAddress((void**)&gv, g_v);
    float* gattn; cudaGetSymbolAddress((void**)&gattn, g_attn);
    float* gemb2; cudaGetSymbolAddress((void**)&gemb2, g_emb2);
    float* gy;    cudaGetSymbolAddress((void**)&gy, g_y);

    reset_kernel<<<(kSlots + 255) / 256, 256>>>();
    ln_kernel<<<kT, 256>>>(emb, gamma1, beta1, gx);
    qkv_kernel<<<dim3(kT / 128, (kH * kDH) / 128, 3), 256>>>(gx, WQ, WK, WV, gq, gk, gv);
    attn_kernel<<<(kH * kT) / 8, 256>>>(gq, gk, gv, gattn);
    proj_kernel<<<dim3(kT / 128, kD / 128), 256>>>(gattn, Wproj, bproj, emb, gemb2);
    ln_kernel<<<kT, 256>>>(gemb2, gamma2, beta2, gy);
    router_kernel<<<kT / 8, 256>>>(gy, Wr, br);
    offsets_kernel<<<1, 32>>>(out, out_size);
    scatter_kernel<<<(kT * 2 + 255) / 256, 256>>>();
    f1_kernel<<<dim3(kSlots / 128, kDFF / 128), 256>>>(gy, W1, b1);
    f2_kernel<<<dim3(kSlots / 128, kD / 128), 256>>>(W2, b2);
    combine_kernel<<<(kT * kD / 4 + 255) / 256, 256>>>(out);
}

// round 5
// speedup vs baseline: 2.9700x; 1.7194x over previous
#include <cuda_runtime.h>
#include <math.h>

// ---------------- problem constants ----------------
constexpr int kT   = 1024;
constexpr int kD   = 1024;
constexpr int kH   = 16;
constexpr int kDH  = 64;
constexpr int kE   = 8;
constexpr int kDFF = 4096;
constexpr int kSlots = 3072;   // 2048 assignments + per-expert pad to 128

// ---------------- device scratch ----------------
__device__ float g_x[kT * kD];
__device__ float g_q[kH * kT * kDH];
__device__ float g_kT[kH * kDH * kT];   // K transposed: [h][dh][t]
__device__ float g_v[kH * kT * kDH];
__device__ float g_attn[kT * kD];
__device__ float g_emb2[kT * kD];
__device__ float g_y[kT * kD];
__device__ float g_h[kSlots * kDFF];
__device__ float g_yo[kSlots * kD];
__device__ int   g_ids[kT * 2];
__device__ float g_gates[kT * 2];
__device__ int   g_counts[kE];
__device__ int   g_poff[kE + 1];
__device__ int   g_cursor[kE];
__device__ int   g_slot_token[kSlots];
__device__ int   g_slotpos[kT * 2];
__device__ float g_impsum[kE];

// ---------------- mma helpers ----------------
__device__ __forceinline__ unsigned f2tf32(float x) {
    unsigned y; asm("cvt.rna.tf32.f32 %0, %1;" : "=r"(y) : "f"(x)); return y;
}
__device__ __forceinline__ void mma_tf32(float c[4], const unsigned a[4], const unsigned b[2]) {
    asm volatile("mma.sync.aligned.m16n8k8.row.col.f32.tf32.tf32.f32 "
        "{%0,%1,%2,%3}, {%4,%5,%6,%7}, {%8,%9}, {%0,%1,%2,%3};\n"
        : "+f"(c[0]), "+f"(c[1]), "+f"(c[2]), "+f"(c[3])
        : "r"(a[0]), "r"(a[1]), "r"(a[2]), "r"(a[3]), "r"(b[0]), "r"(b[1]));
}

// Shared GEMM tile config: block 256 threads, tile M=128 N=128, K-panel 32.
constexpr int ASTRIDE = 36;
constexpr int BSTRIDE = 136;

#define GEMM_SMEM \
    __shared__ __align__(16) unsigned As[128 * ASTRIDE]; \
    __shared__ __align__(16) unsigned Bs[32 * BSTRIDE];

#define GEMM_COMPUTE_PANEL \
    _Pragma("unroll") \
    for (int kk = 0; kk < 32; kk += 8) { \
        unsigned bf[8][2]; \
        _Pragma("unroll") \
        for (int nt = 0; nt < 8; nt++) { \
            int n = wn * 64 + nt * 8 + (lane >> 2); \
            bf[nt][0] = Bs[(kk + (lane & 3)) * BSTRIDE + n]; \
            bf[nt][1] = Bs[(kk + 4 + (lane & 3)) * BSTRIDE + n]; \
        } \
        _Pragma("unroll") \
        for (int mt = 0; mt < 2; mt++) { \
            int m = wm * 32 + mt * 16 + (lane >> 2); \
            unsigned af[4]; \
            af[0] = As[m * ASTRIDE + kk + (lane & 3)]; \
            af[1] = As[(m + 8) * ASTRIDE + kk + (lane & 3)]; \
            af[2] = As[m * ASTRIDE + kk + 4 + (lane & 3)]; \
            af[3] = As[(m + 8) * ASTRIDE + kk + 4 + (lane & 3)]; \
            _Pragma("unroll") \
            for (int nt = 0; nt < 8; nt++) mma_tf32(acc[mt][nt], af, bf[nt]); \
        } \
    }

__device__ __forceinline__ void store_a_frag4(unsigned* As, int m, int kv4, float4 v) {
    uint4 u = { f2tf32(v.x), f2tf32(v.y), f2tf32(v.z), f2tf32(v.w) };
    *(uint4*)&As[m * ASTRIDE + kv4] = u;
}
__device__ __forceinline__ void store_b_frag4(unsigned* Bs, int k, int nv4, float4 v) {
    uint4 u = { f2tf32(v.x), f2tf32(v.y), f2tf32(v.z), f2tf32(v.w) };
    *(uint4*)&Bs[k * BSTRIDE + nv4] = u;
}

// ---------------- misc helpers ----------------
__device__ __forceinline__ float block_reduce_sum(float v) {
    __shared__ float sh[32];
    int lane = threadIdx.x & 31, w = threadIdx.x >> 5;
    #pragma unroll
    for (int o = 16; o > 0; o >>= 1) v += __shfl_xor_sync(0xffffffffu, v, o);
    if (lane == 0) sh[w] = v;
    __syncthreads();
    if (w == 0) {
        v = (lane < (int)(blockDim.x >> 5)) ? sh[lane] : 0.f;
        #pragma unroll
        for (int o = 16; o > 0; o >>= 1) v += __shfl_xor_sync(0xffffffffu, v, o);
        if (lane == 0) sh[0] = v;
    }
    __syncthreads();
    float r = sh[0];
    __syncthreads();
    return r;
}

__global__ void reset_kernel() {
    int i = blockIdx.x * blockDim.x + threadIdx.x;
    if (i < kSlots) g_slot_token[i] = -1;
    if (i < kE) { g_counts[i] = 0; g_impsum[i] = 0.f; }
}

__global__ void ln_kernel(const float* __restrict__ in, const float* __restrict__ g,
                          const float* __restrict__ b, float* __restrict__ out) {
    int row = blockIdx.x;
    const float* x = in + (size_t)row * kD;
    float s = 0.f;
    for (int i = threadIdx.x; i < kD; i += blockDim.x) s += x[i];
    float mean = block_reduce_sum(s) * (1.f / kD);
    float v = 0.f;
    for (int i = threadIdx.x; i < kD; i += blockDim.x) {
        float d = x[i] - mean; v += d * d;
    }
    float var = block_reduce_sum(v) * (1.f / kD);
    float rstd = rsqrtf(var + 1e-6f);
    float* o = out + (size_t)row * kD;
    for (int i = threadIdx.x; i < kD; i += blockDim.x)
        o[i] = (x[i] - mean) * rstd * g[i] + b[i];
}

// ---------------- QKV tf32 GEMM + fused RoPE (K written transposed) ----------------
__global__ __launch_bounds__(256) void qkv_kernel(
    const float* __restrict__ x,
    const float* __restrict__ WQ, const float* __restrict__ WK, const float* __restrict__ WV,
    float* __restrict__ Qo, float* __restrict__ KTo, float* __restrict__ Vo) {
    GEMM_SMEM
    int tid = threadIdx.x, lane = tid & 31, w = tid >> 5;
    int wm = w & 3, wn = w >> 2;
    int r0 = blockIdx.x * 128;
    int n0 = blockIdx.y * 128;
    int z = blockIdx.z;
    const float* W = (z == 0) ? WQ : (z == 1) ? WK : WV;

    float acc[2][8][4] = {};
    for (int k0 = 0; k0 < kD; k0 += 32) {
        #pragma unroll
        for (int p = 0; p < 4; p++) {
            int m = (tid >> 3) + p * 32, kv = (tid & 7) * 4;
            float4 v = *(const float4*)&x[(size_t)(r0 + m) * kD + k0 + kv];
            store_a_frag4(As, m, kv, v);
        }
        #pragma unroll
        for (int p = 0; p < 4; p++) {
            int kr = (tid >> 5) + p * 8, nv = (tid & 31) * 4;
            int n = n0 + nv;
            int h = n >> 6, e = n & 63;
            float4 v = *(const float4*)&W[((size_t)h * kD + k0 + kr) * kDH + e];
            store_b_frag4(Bs, kr, nv, v);
        }
        __syncthreads();
        GEMM_COMPUTE_PANEL
        __syncthreads();
    }
    #pragma unroll
    for (int mt = 0; mt < 2; mt++) {
        #pragma unroll
        for (int nt = 0; nt < 8; nt++) {
            int n = n0 + wn * 64 + nt * 8 + (lane & 3) * 2;
            int h = n >> 6, e = n & 63;
            #pragma unroll
            for (int half = 0; half < 2; half++) {
                int t = r0 + wm * 32 + mt * 16 + (lane >> 2) + half * 8;
                float v0 = acc[mt][nt][half * 2 + 0];
                float v1 = acc[mt][nt][half * 2 + 1];
                if (z < 2) {
                    int p = e >> 1;
                    float theta = exp2f(-(float)p * (13.287712379549449f / 32.f));
                    float sn, cs;
                    sincosf((float)t * theta, &sn, &cs);
                    float w0 = v0 * cs - v1 * sn;
                    float w1 = v1 * cs + v0 * sn;
                    v0 = w0; v1 = w1;
                }
                if (z == 1) {
                    KTo[((size_t)h * kDH + e) * kT + t]     = v0;
                    KTo[((size_t)h * kDH + e + 1) * kT + t] = v1;
                } else {
                    float* O = (z == 0) ? Qo : Vo;
                    float2 r2 = { v0, v1 };
                    *(float2*)&O[((size_t)h * kT + t) * kDH + e] = r2;
                }
            }
        }
    }
}

// ---------------- flash attention: block = (64 q-rows, head), 4 warps ----------------
constexpr int KSTR = 72;   // Ks/Vs row stride (conflict-free both sides)
constexpr int PSTR = 68;   // Qs/Ps row stride (64 cols + pad; 68%32=4 -> conflict-free frags)
constexpr int ATTN_SMEM_BYTES = (64 * PSTR + 2 * 64 * KSTR) * 4;   // 54272

__global__ __launch_bounds__(128) void attn_kernel(
    const float* __restrict__ Q, const float* __restrict__ KTr,
    const float* __restrict__ V, float* __restrict__ A) {
    extern __shared__ __align__(16) unsigned sm_attn[];
    unsigned* QPs = sm_attn;                 // 64 x PSTR : Q staging, then P tiles
    unsigned* Ks  = sm_attn + 64 * PSTR;     // 64 x KSTR : [dh][key]
    unsigned* Vs  = Ks + 64 * KSTR;          // 64 x KSTR : [key][dh]
    int tid = threadIdx.x, lane = tid & 31, w = tid >> 5;
    int h = blockIdx.y;
    int qt = (int)gridDim.x - 1 - (int)blockIdx.x;   // heavy tiles first
    int q0 = qt * 64;
    const float* Qh  = Q   + ((size_t)h * kT + q0) * kDH;
    const float* KTh = KTr + (size_t)h * kDH * kT;
    const float* Vh  = V   + (size_t)h * kT * kDH;

    // stage Q tile (tf32)
    #pragma unroll
    for (int it = 0; it < 8; it++) {
        int idx = tid + it * 128;
        int m = idx >> 4, dh4 = (idx & 15) * 4;
        float4 v = *(const float4*)&Qh[(size_t)m * kDH + dh4];
        uint4 u = { f2tf32(v.x), f2tf32(v.y), f2tf32(v.z), f2tf32(v.w) };
        *(uint4*)&QPs[m * PSTR + dh4] = u;
    }
    __syncthreads();
    // per-warp Q fragments (rows w*16 .. w*16+15), kept in registers
    unsigned qf[8][4];
    {
        int m = w * 16 + (lane >> 2);
        #pragma unroll
        for (int kk = 0; kk < 8; kk++) {
            qf[kk][0] = QPs[m * PSTR + kk * 8 + (lane & 3)];
            qf[kk][1] = QPs[(m + 8) * PSTR + kk * 8 + (lane & 3)];
            qf[kk][2] = QPs[m * PSTR + kk * 8 + 4 + (lane & 3)];
            qf[kk][3] = QPs[(m + 8) * PSTR + kk * 8 + 4 + (lane & 3)];
        }
    }

    float acc_o[8][4] = {};
    float m0 = -1e30f, m1 = -1e30f, l0 = 0.f, l1 = 0.f;

    for (int kt = 0; kt <= qt; kt++) {
        int k0 = kt * 64;
        __syncthreads();   // previous tile's reads done (and Q frag reads on iter 0)
        // load K^T tile: Ks[dh][key]
        #pragma unroll
        for (int it = 0; it < 8; it++) {
            int idx = tid + it * 128;
            int dh = idx >> 4, key4 = (idx & 15) * 4;
            float4 v = *(const float4*)&KTh[(size_t)dh * kT + k0 + key4];
            uint4 u = { f2tf32(v.x), f2tf32(v.y), f2tf32(v.z), f2tf32(v.w) };
            *(uint4*)&Ks[dh * KSTR + key4] = u;
        }
        // load V tile: Vs[key][dh]
        #pragma unroll
        for (int it = 0; it < 8; it++) {
            int idx = tid + it * 128;
            int key = idx >> 4, dh4 = (idx & 15) * 4;
            float4 v = *(const float4*)&Vh[(size_t)(k0 + key) * kDH + dh4];
            uint4 u = { f2tf32(v.x), f2tf32(v.y), f2tf32(v.z), f2tf32(v.w) };
            *(uint4*)&Vs[key * KSTR + dh4] = u;
        }
        __syncthreads();

        // S = Q @ K^T  (per warp: 16 x 64)
        float s_acc[8][4] = {};
        #pragma unroll
        for (int kk = 0; kk < 8; kk++) {
            #pragma unroll
            for (int nt = 0; nt < 8; nt++) {
                unsigned bf[2];
                bf[0] = Ks[(kk * 8 + (lane & 3)) * KSTR + nt * 8 + (lane >> 2)];
                bf[1] = Ks[(kk * 8 + 4 + (lane & 3)) * KSTR + nt * 8 + (lane >> 2)];
                mma_tf32(s_acc[nt], qf[kk], bf);
            }
        }

        // scale + causal mask + row max
        float rm0 = -1e30f, rm1 = -1e30f;
        int gq0 = q0 + w * 16 + (lane >> 2);
        #pragma unroll
        for (int nt = 0; nt < 8; nt++) {
            #pragma unroll
            for (int c = 0; c < 4; c++) {
                float v = s_acc[nt][c] * 0.125f;
                if (kt == qt) {
                    int key = k0 + nt * 8 + 2 * (lane & 3) + (c & 1);
                    int gq = gq0 + (c >> 1) * 8;
                    if (key > gq) v = -1e30f;
                }
                s_acc[nt][c] = v;
                if ((c >> 1) == 0) rm0 = fmaxf(rm0, v); else rm1 = fmaxf(rm1, v);
            }
        }
        #pragma unroll
        for (int o = 1; o <= 2; o <<= 1) {
            rm0 = fmaxf(rm0, __shfl_xor_sync(0xffffffffu, rm0, o));
            rm1 = fmaxf(rm1, __shfl_xor_sync(0xffffffffu, rm1, o));
        }
        float nm0 = fmaxf(m0, rm0), nm1 = fmaxf(m1, rm1);
        float sc0 = __expf(m0 - nm0), sc1 = __expf(m1 - nm1);
        m0 = nm0; m1 = nm1;

        // P = exp(S - m), row sums, store P to smem (tf32)
        float rs0 = 0.f, rs1 = 0.f;
        int prow = w * 16 + (lane >> 2);
        #pragma unroll
        for (int nt = 0; nt < 8; nt++) {
            float p0 = __expf(s_acc[nt][0] - nm0);
            float p1 = __expf(s_acc[nt][1] - nm0);
            float p2 = __expf(s_acc[nt][2] - nm1);
            float p3 = __expf(s_acc[nt][3] - nm1);
            rs0 += p0 + p1; rs1 += p2 + p3;
            uint2 u01 = { f2tf32(p0), f2tf32(p1) };
            uint2 u23 = { f2tf32(p2), f2tf32(p3) };
            *(uint2*)&QPs[prow * PSTR + nt * 8 + 2 * (lane & 3)] = u01;
            *(uint2*)&QPs[(prow + 8) * PSTR + nt * 8 + 2 * (lane & 3)] = u23;
        }
        #pragma unroll
        for (int o = 1; o <= 2; o <<= 1) {
            rs0 += __shfl_xor_sync(0xffffffffu, rs0, o);
            rs1 += __shfl_xor_sync(0xffffffffu, rs1, o);
        }
        l0 = l0 * sc0 + rs0;
        l1 = l1 * sc1 + rs1;
        #pragma unroll
        for (int nt = 0; nt < 8; nt++) {
            acc_o[nt][0] *= sc0; acc_o[nt][1] *= sc0;
            acc_o[nt][2] *= sc1; acc_o[nt][3] *= sc1;
        }
        __syncwarp();

        // O += P @ V  (per warp: 16 x 64, k = 64 keys)
        #pragma unroll
        for (int kk = 0; kk < 8; kk++) {
            unsigned pf[4];
            int m = w * 16 + (lane >> 2);
            pf[0] = QPs[m * PSTR + kk * 8 + (lane & 3)];
            pf[1] = QPs[(m + 8) * PSTR + kk * 8 + (lane & 3)];
            pf[2] = QPs[m * PSTR + kk * 8 + 4 + (lane & 3)];
            pf[3] = QPs[(m + 8) * PSTR + kk * 8 + 4 + (lane & 3)];
            #pragma unroll
            for (int nt = 0; nt < 8; nt++) {
                unsigned bf[2];
                bf[0] = Vs[(kk * 8 + (lane & 3)) * KSTR + nt * 8 + (lane >> 2)];
                bf[1] = Vs[(kk * 8 + 4 + (lane & 3)) * KSTR + nt * 8 + (lane >> 2)];
                mma_tf32(acc_o[nt], pf, bf);
            }
        }
    }

    // write O
    float inv0 = 1.f / l0, inv1 = 1.f / l1;
    int gq0 = q0 + w * 16 + (lane >> 2);
    #pragma unroll
    for (int nt = 0; nt < 8; nt++) {
        int col = h * kDH + nt * 8 + 2 * (lane & 3);
        float2 r0 = { acc_o[nt][0] * inv0, acc_o[nt][1] * inv0 };
        float2 r1 = { acc_o[nt][2] * inv1, acc_o[nt][3] * inv1 };
        *(float2*)&A[(size_t)gq0 * kD + col] = r0;
        *(float2*)&A[(size_t)(gq0 + 8) * kD + col] = r1;
    }
}

// ---------------- proj tf32 GEMM + residual ----------------
__global__ __launch_bounds__(256) void proj_kernel(
    const float* __restrict__ A, const float* __restrict__ W,
    const float* __restrict__ bias, const float* __restrict__ emb,
    float* __restrict__ out) {
    GEMM_SMEM
    int tid = threadIdx.x, lane = tid & 31, w = tid >> 5;
    int wm = w & 3, wn = w >> 2;
    int r0 = blockIdx.x * 128;
    int n0 = blockIdx.y * 128;

    float acc[2][8][4] = {};
    for (int k0 = 0; k0 < kD; k0 += 32) {
        #pragma unroll
        for (int p = 0; p < 4; p++) {
            int m = (tid >> 3) + p * 32, kv = (tid & 7) * 4;
            float4 v = *(const float4*)&A[(size_t)(r0 + m) * kD + k0 + kv];
            store_a_frag4(As, m, kv, v);
        }
        #pragma unroll
        for (int p = 0; p < 4; p++) {
            int kr = (tid >> 5) + p * 8, nv = (tid & 31) * 4;
            float4 v = *(const float4*)&W[(size_t)(k0 + kr) * kD + n0 + nv];
            store_b_frag4(Bs, kr, nv, v);
        }
        __syncthreads();
        GEMM_COMPUTE_PANEL
        __syncthreads();
    }
    #pragma unroll
    for (int mt = 0; mt < 2; mt++) {
        #pragma unroll
        for (int nt = 0; nt < 8; nt++) {
            int c = n0 + wn * 64 + nt * 8 + (lane & 3) * 2;
            #pragma unroll
            for (int half = 0; half < 2; half++) {
                int r = r0 + wm * 32 + mt * 16 + (lane >> 2) + half * 8;
                float2 e2 = *(const float2*)&emb[(size_t)r * kD + c];
                float2 r2;
                r2.x = e2.x + acc[mt][nt][half * 2 + 0] + bias[c];
                r2.y = e2.y + acc[mt][nt][half * 2 + 1] + bias[c + 1];
                *(float2*)&out[(size_t)r * kD + c] = r2;
            }
        }
    }
}

// ---------------- router ----------------
__global__ void router_kernel(const float* __restrict__ y, const float* __restrict__ Wr,
                              const float* __restrict__ br) {
    int warp = (blockIdx.x * blockDim.x + threadIdx.x) >> 5;
    int lane = threadIdx.x & 31;
    if (warp >= kT) return;
    const float* yr = y + (size_t)warp * kD;
    float s[kE];
    #pragma unroll
    for (int e = 0; e < kE; e++) s[e] = 0.f;
    for (int d = lane; d < kD; d += 32) {
        float yv = yr[d];
        const float* wr = Wr + (size_t)d * kE;
        #pragma unroll
        for (int e = 0; e < kE; e++) s[e] += yv * wr[e];
    }
    #pragma unroll
    for (int e = 0; e < kE; e++) {
        float v = s[e];
        #pragma unroll
        for (int o = 16; o > 0; o >>= 1) v += __shfl_xor_sync(0xffffffffu, v, o);
        s[e] = v;
    }
    if (lane == 0) {
        float w[kE];
        float mx = -1e30f;
        #pragma unroll
        for (int e = 0; e < kE; e++) { w[e] = s[e] + br[e]; mx = fmaxf(mx, w[e]); }
        float sum = 0.f;
        #pragma unroll
        for (int e = 0; e < kE; e++) { w[e] = __expf(w[e] - mx); sum += w[e]; }
        float inv = 1.f / sum;
        #pragma unroll
        for (int e = 0; e < kE; e++) w[e] *= inv;
        int i0 = 0;
        #pragma unroll
        for (int e = 1; e < kE; e++) if (w[e] > w[i0]) i0 = e;
        int i1 = -1;
        #pragma unroll
        for (int e = 0; e < kE; e++) if (e != i0 && (i1 < 0 || w[e] > w[i1])) i1 = e;
        float norm = w[i0] + w[i1];
        g_ids[warp * 2]     = i0;
        g_ids[warp * 2 + 1] = i1;
        g_gates[warp * 2]     = w[i0] / norm;
        g_gates[warp * 2 + 1] = w[i1] / norm;
        atomicAdd(&g_counts[i0], 1);
        atomicAdd(&g_counts[i1], 1);
        #pragma unroll
        for (int e = 0; e < kE; e++) atomicAdd(&g_impsum[e], w[e]);
    }
}

__global__ void offsets_kernel(float* __restrict__ out, int out_size) {
    if (threadIdx.x == 0 && blockIdx.x == 0) {
        int off = 0;
        g_poff[0] = 0;
        for (int e = 0; e < kE; e++) {
            int pc = (g_counts[e] + 127) & ~127;
            off += pc;
            g_poff[e + 1] = off;
            g_cursor[e] = g_poff[e];
        }
        float aux = 0.f;
        for (int e = 0; e < kE; e++) {
            float imp = g_impsum[e] / (float)kT;
            float dlt = imp - 1.f / (float)kE;
            aux += dlt * dlt;
        }
        aux *= 1.f / (float)kE;
        if (out_size > kT * kD) out[kT * kD] = aux;
    }
}

__global__ void scatter_kernel() {
    int i = blockIdx.x * blockDim.x + threadIdx.x;
    if (i >= kT * 2) return;
    int e = g_ids[i];
    int pos = atomicAdd(&g_cursor[e], 1);
    g_slot_token[pos] = i >> 1;
    g_slotpos[i] = pos;
}

// ---------------- F1: h = relu(y_gathered @ W1[e] + b1[e]) tf32 ----------------
__global__ __launch_bounds__(256) void f1_kernel(
    const float* __restrict__ y, const float* __restrict__ W1,
    const float* __restrict__ b1) {
    GEMM_SMEM
    __shared__ int tok[128];
    __shared__ int sh_total, sh_e;
    int tid = threadIdx.x, lane = tid & 31, w = tid >> 5;
    int wm = w & 3, wn = w >> 2;
    int s0 = blockIdx.x * 128;
    if (tid == 0) {
        sh_total = g_poff[kE];
        int e = 0;
        while (e < kE - 1 && s0 >= g_poff[e + 1]) e++;
        sh_e = e;
    }
    if (tid < 128) tok[tid] = g_slot_token[s0 + tid];
    __syncthreads();
    if (s0 >= sh_total) return;
    int e = sh_e;
    const float* W = W1 + (size_t)e * kD * kDFF;
    int f0 = blockIdx.y * 128;

    float acc[2][8][4] = {};
    for (int k0 = 0; k0 < kD; k0 += 32) {
        #pragma unroll
        for (int p = 0; p < 4; p++) {
            int m = (tid >> 3) + p * 32, kv = (tid & 7) * 4;
            int t = tok[m];
            float4 v = (t >= 0) ? *(const float4*)&y[(size_t)t * kD + k0 + kv]
                                : make_float4(0.f, 0.f, 0.f, 0.f);
            store_a_frag4(As, m, kv, v);
        }
        #pragma unroll
        for (int p = 0; p < 4; p++) {
            int kr = (tid >> 5) + p * 8, nv = (tid & 31) * 4;
            float4 v = *(const float4*)&W[(size_t)(k0 + kr) * kDFF + f0 + nv];
            store_b_frag4(Bs, kr, nv, v);
        }
        __syncthreads();
        GEMM_COMPUTE_PANEL
        __syncthreads();
    }
    #pragma unroll
    for (int mt = 0; mt < 2; mt++) {
        #pragma unroll
        for (int nt = 0; nt < 8; nt++) {
            int c = f0 + wn * 64 + nt * 8 + (lane & 3) * 2;
            float bb0 = b1[(size_t)e * kDFF + c];
            float bb1 = b1[(size_t)e * kDFF + c + 1];
            #pragma unroll
            for (int half = 0; half < 2; half++) {
                int r = s0 + wm * 32 + mt * 16 + (lane >> 2) + half * 8;
                float2 r2;
                r2.x = fmaxf(acc[mt][nt][half * 2 + 0] + bb0, 0.f);
                r2.y = fmaxf(acc[mt][nt][half * 2 + 1] + bb1, 0.f);
                *(float2*)&g_h[(size_t)r * kDFF + c] = r2;
            }
        }
    }
}

// ---------------- F2: yo = h @ W2[e] + b2[e] tf32 ----------------
__global__ __launch_bounds__(256) void f2_kernel(
    const float* __restrict__ W2, const float* __restrict__ b2) {
    GEMM_SMEM
    __shared__ int sh_total, sh_e;
    int tid = threadIdx.x, lane = tid & 31, w = tid >> 5;
    int wm = w & 3, wn = w >> 2;
    int s0 = blockIdx.x * 128;
    if (tid == 0) {
        sh_total = g_poff[kE];
        int e = 0;
        while (e < kE - 1 && s0 >= g_poff[e + 1]) e++;
        sh_e = e;
    }
    __syncthreads();
    if (s0 >= sh_total) return;
    int e = sh_e;
    const float* W = W2 + (size_t)e * kDFF * kD;
    int c0 = blockIdx.y * 128;

    float acc[2][8][4] = {};
    for (int k0 = 0; k0 < kDFF; k0 += 32) {
        #pragma unroll
        for (int p = 0; p < 4; p++) {
            int m = (tid >> 3) + p * 32, kv = (tid & 7) * 4;
            float4 v = *(const float4*)&g_h[(size_t)(s0 + m) * kDFF + k0 + kv];
            store_a_frag4(As, m, kv, v);
        }
        #pragma unroll
        for (int p = 0; p < 4; p++) {
            int kr = (tid >> 5) + p * 8, nv = (tid & 31) * 4;
            float4 v = *(const float4*)&W[(size_t)(k0 + kr) * kD + c0 + nv];
            store_b_frag4(Bs, kr, nv, v);
        }
        __syncthreads();
        GEMM_COMPUTE_PANEL
        __syncthreads();
    }
    #pragma unroll
    for (int mt = 0; mt < 2; mt++) {
        #pragma unroll
        for (int nt = 0; nt < 8; nt++) {
            int c = c0 + wn * 64 + nt * 8 + (lane & 3) * 2;
            float bb0 = b2[(size_t)e * kD + c];
            float bb1 = b2[(size_t)e * kD + c + 1];
            #pragma unroll
            for (int half = 0; half < 2; half++) {
                int r = s0 + wm * 32 + mt * 16 + (lane >> 2) + half * 8;
                float2 r2;
                r2.x = acc[mt][nt][half * 2 + 0] + bb0;
                r2.y = acc[mt][nt][half * 2 + 1] + bb1;
                *(float2*)&g_yo[(size_t)r * kD + c] = r2;
            }
        }
    }
}

// ---------------- combine ----------------
__global__ void combine_kernel(float* __restrict__ out) {
    int idx4 = blockIdx.x * blockDim.x + threadIdx.x;
    if (idx4 >= kT * kD / 4) return;
    int idx = idx4 * 4;
    int n = idx >> 10;
    int d = idx & (kD - 1);
    int p0 = g_slotpos[n * 2], p1 = g_slotpos[n * 2 + 1];
    float g0 = g_gates[n * 2], g1 = g_gates[n * 2 + 1];
    float4 base = *(const float4*)&g_emb2[idx];
    float4 y0 = *(const float4*)&g_yo[(size_t)p0 * kD + d];
    float4 y1 = *(const float4*)&g_yo[(size_t)p1 * kD + d];
    float4 r;
    r.x = base.x + g0 * y0.x + g1 * y1.x;
    r.y = base.y + g0 * y0.y + g1 * y1.y;
    r.z = base.z + g0 * y0.z + g1 * y1.z;
    r.w = base.w + g0 * y0.w + g1 * y1.w;
    *(float4*)&out[idx] = r;
}

// ---------------- launch ----------------
extern "C" void kernel_launch(void* const* d_in, const int* in_sizes, int n_in,
                              void* d_out, int out_size) {
    const float* emb    = (const float*)d_in[0];
    const float* gamma1 = (const float*)d_in[1];
    const float* beta1  = (const float*)d_in[2];
    const float* WQ     = (const float*)d_in[3];
    const float* WK     = (const float*)d_in[4];
    const float* WV     = (const float*)d_in[5];
    const float* Wproj  = (const float*)d_in[6];
    const float* bproj  = (const float*)d_in[7];
    const float* gamma2 = (const float*)d_in[8];
    const float* beta2  = (const float*)d_in[9];
    const float* Wr     = (const float*)d_in[10];
    const float* br     = (const float*)d_in[11];
    const float* W1     = (const float*)d_in[12];
    const float* b1     = (const float*)d_in[13];
    const float* W2     = (const float*)d_in[14];
    const float* b2     = (const float*)d_in[15];
    float* out = (float*)d_out;

    float* gx;    cudaGetSymbolAddress((void**)&gx, g_x);
    float* gq;    cudaGetSymbolAddress((void**)&gq, g_q);
    float* gkT;   cudaGetSymbolAddress((void**)&gkT, g_kT);
    float* gv;    cudaGetSymbolAddress((void**)&gv, g_v);
    float* gattn; cudaGetSymbolAddress((void**)&gattn, g_attn);
    float* gemb2; cudaGetSymbolAddress((void**)&gemb2, g_emb2);
    float* gy;    cudaGetSymbolAddress((void**)&gy, g_y);

    cudaFuncSetAttribute(attn_kernel, cudaFuncAttributeMaxDynamicSharedMemorySize,
                         ATTN_SMEM_BYTES);

    reset_kernel<<<(kSlots + 255) / 256, 256>>>();
    ln_kernel<<<kT, 256>>>(emb, gamma1, beta1, gx);
    qkv_kernel<<<dim3(kT / 128, (kH * kDH) / 128, 3), 256>>>(gx, WQ, WK, WV, gq, gkT, gv);
    attn_kernel<<<dim3(kT / 64, kH), 128, ATTN_SMEM_BYTES>>>(gq, gkT, gv, gattn);
    proj_kernel<<<dim3(kT / 128, kD / 128), 256>>>(gattn, Wproj, bproj, emb, gemb2);
    ln_kernel<<<kT, 256>>>(gemb2, gamma2, beta2, gy);
    router_kernel<<<kT / 8, 256>>>(gy, Wr, br);
    offsets_kernel<<<1, 32>>>(out, out_size);
    scatter_kernel<<<(kT * 2 + 255) / 256, 256>>>();
    f1_kernel<<<dim3(kSlots / 128, kDFF / 128), 256>>>(gy, W1, b1);
    f2_kernel<<<dim3(kSlots / 128, kD / 128), 256>>>(W2, b2);
    combine_kernel<<<(kT * kD / 4 + 255) / 256, 256>>>(out);
}